// round 11
// baseline (speedup 1.0000x reference)
#include <cuda_runtime.h>
#include <cuda_bf16.h>
#include <math.h>

#define CB 4
#define CT 2048
#define CD 1024
#define CH 8
#define CHD 128
#define CM (CB * CT)
#define YTOT (CM * CD)
#define STOT (CB * CH * CHD * CHD)
#define RES_SCALE 0.5f
#define NPAIR 1024

#define W_QW 0
#define W_KW (1024 * 1024)
#define W_VW (2 * 1024 * 1024)
#define W_GW (3 * 1024 * 1024)
#define W_OW (4 * 1024 * 1024)
#define W_FCW (5 * 1024 * 1024)
#define W_PW (9 * 1024 * 1024)
#define W_TOT (13 * 1024 * 1024)

__device__ float g_h[CM * CD];
__device__ float g_q[CM * CD];
__device__ float g_k[CM * CD];
__device__ float g_v[CM * CD];
__device__ float g_gate[CM * CD];
__device__ float g_o[CM * CD];
__device__ float g_attn[CM * CD];
__device__ float g_x1[CM * CD];
__device__ float g_beta[CM * CH];
__device__ float g_eg[CM * CH];
__device__ float g_dots[CB * NPAIR * CH * 4];
__device__ float g_sfdummy[STOT];

__device__ __nv_bfloat16 g_hh[CM * CD];
__device__ __nv_bfloat16 g_hl[CM * CD];
__device__ __nv_bfloat16 g_h2h[CM * CD];
__device__ __nv_bfloat16 g_h2l[CM * CD];
__device__ __nv_bfloat16 g_oh[CM * CD];
__device__ __nv_bfloat16 g_ol[CM * CD];
__device__ __nv_bfloat16 g_mlph[CM * 4 * CD];
__device__ __nv_bfloat16 g_mlpl[CM * 4 * CD];
__device__ __nv_bfloat16 g_wth[W_TOT];
__device__ __nv_bfloat16 g_wtl[W_TOT];

__device__ __forceinline__ float siluf(float x) { return x / (1.0f + expf(-x)); }

__device__ __forceinline__ float warpAllSum(float v) {
    v += __shfl_xor_sync(0xffffffffu, v, 16);
    v += __shfl_xor_sync(0xffffffffu, v, 8);
    v += __shfl_xor_sync(0xffffffffu, v, 4);
    v += __shfl_xor_sync(0xffffffffu, v, 2);
    v += __shfl_xor_sync(0xffffffffu, v, 1);
    return v;
}

__device__ __forceinline__ void split_pair(float a, float b,
                                           __nv_bfloat16* hi, __nv_bfloat16* lo) {
    __nv_bfloat16 h0 = __float2bfloat16(a);
    __nv_bfloat16 h1 = __float2bfloat16(b);
    float r0 = a - __bfloat162float(h0);
    float r1 = b - __bfloat162float(h1);
    __nv_bfloat162 hv; hv.x = h0; hv.y = h1;
    __nv_bfloat162 lv; lv.x = __float2bfloat16(r0); lv.y = __float2bfloat16(r1);
    *(__nv_bfloat162*)hi = hv;
    *(__nv_bfloat162*)lo = lv;
}

__device__ __forceinline__ void cpa16(unsigned dst, const void* src) {
    asm volatile("cp.async.ca.shared.global [%0], [%1], 16;" :: "r"(dst), "l"(src));
}
__device__ __forceinline__ void cpa4(unsigned dst, const void* src) {
    asm volatile("cp.async.ca.shared.global [%0], [%1], 4;" :: "r"(dst), "l"(src));
}

__device__ __forceinline__ void mma16816(float* c, const unsigned* a, const unsigned* b) {
    asm volatile(
        "mma.sync.aligned.m16n8k16.row.col.f32.bf16.bf16.f32 "
        "{%0,%1,%2,%3},{%4,%5,%6,%7},{%8,%9},{%0,%1,%2,%3};"
        : "+f"(c[0]), "+f"(c[1]), "+f"(c[2]), "+f"(c[3])
        : "r"(a[0]), "r"(a[1]), "r"(a[2]), "r"(a[3]), "r"(b[0]), "r"(b[1]));
}
__device__ __forceinline__ void ldsm4(unsigned* d, unsigned addr) {
    asm volatile("ldmatrix.sync.aligned.m8n8.x4.shared.b16 {%0,%1,%2,%3}, [%4];"
                 : "=r"(d[0]), "=r"(d[1]), "=r"(d[2]), "=r"(d[3]) : "r"(addr));
}
__device__ __forceinline__ void ldsm2(unsigned* d, unsigned addr) {
    asm volatile("ldmatrix.sync.aligned.m8n8.x2.shared.b16 {%0,%1}, [%2];"
                 : "=r"(d[0]), "=r"(d[1]) : "r"(addr));
}

// -------------------- pipelined tensor-core GEMM --------------------------
// EPI 0: fp32 out. 1: silu -> bf16 hi/lo. 2: silu + per-head l2norm -> fp32.
// 3: silu -> fp32. 4: out = X1 + 0.5*acc -> fp32.
#define SSTRIDE 40
#define GPLANE (128 * SSTRIDE)
#define GSTAGE (4 * GPLANE)
#define GSMEM (2 * GSTAGE * 2)

template <int EPI>
__global__ __launch_bounds__(256, 2) void gemm_tc(
    const __nv_bfloat16* __restrict__ Ahi, const __nv_bfloat16* __restrict__ Alo,
    const __nv_bfloat16* __restrict__ Bhi, const __nv_bfloat16* __restrict__ Blo,
    float* __restrict__ C, __nv_bfloat16* __restrict__ Chi,
    __nv_bfloat16* __restrict__ Clo, const float* __restrict__ X1,
    int M, int N, int K) {
    extern __shared__ __nv_bfloat16 smp[];
    __shared__ float red[128][4];

    int tid = threadIdx.x, warp = tid >> 5, lane = tid & 31;
    int wm = warp >> 2, wn = warp & 3;
    int bm = blockIdx.y * 128, bn = blockIdx.x * 128;
    int lrow = tid >> 1, eoff = (tid & 1) * 16;
    const __nv_bfloat16* pAh = Ahi + (size_t)(bm + lrow) * K + eoff;
    const __nv_bfloat16* pAl = Alo + (size_t)(bm + lrow) * K + eoff;
    const __nv_bfloat16* pBh = Bhi + (size_t)(bn + lrow) * K + eoff;
    const __nv_bfloat16* pBl = Blo + (size_t)(bn + lrow) * K + eoff;
    unsigned sbase = (unsigned)__cvta_generic_to_shared(smp);
    unsigned drow = (unsigned)((lrow * SSTRIDE + eoff) * 2);

    auto issue = [&](int kb, int s) {
        unsigned sb = sbase + (unsigned)(s * (GSTAGE * 2)) + drow;
        cpa16(sb + 0 * (GPLANE * 2), pAh + kb);
        cpa16(sb + 0 * (GPLANE * 2) + 16, pAh + kb + 8);
        cpa16(sb + 1 * (GPLANE * 2), pAl + kb);
        cpa16(sb + 1 * (GPLANE * 2) + 16, pAl + kb + 8);
        cpa16(sb + 2 * (GPLANE * 2), pBh + kb);
        cpa16(sb + 2 * (GPLANE * 2) + 16, pBh + kb + 8);
        cpa16(sb + 3 * (GPLANE * 2), pBl + kb);
        cpa16(sb + 3 * (GPLANE * 2) + 16, pBl + kb + 8);
        asm volatile("cp.async.commit_group;" ::: "memory");
    };
    issue(0, 0);
    issue(32, 1);

    float acc[4][4][4];
#pragma unroll
    for (int i = 0; i < 4; i++)
#pragma unroll
        for (int j = 0; j < 4; j++)
#pragma unroll
            for (int p = 0; p < 4; p++) acc[i][j][p] = 0.0f;

    int sub = lane >> 3, r8 = lane & 7;
    unsigned aoffs = (unsigned)(((wm * 64 + (sub & 1) * 8 + r8) * SSTRIDE + (sub >> 1) * 8) * 2);
    int lb = lane & 15;
    unsigned boffs = (unsigned)(((wn * 32 + (lb & 7)) * SSTRIDE + (lb >> 3) * 8) * 2);

    int nkb = K >> 5;
    for (int it = 0; it < nkb; it++) {
        asm volatile("cp.async.wait_group 1;" ::: "memory");
        __syncthreads();
        unsigned sb = sbase + (unsigned)((it & 1) * (GSTAGE * 2));
        unsigned bAh = sb, bAl = sb + GPLANE * 2;
        unsigned bBh = sb + 2 * (GPLANE * 2), bBl = sb + 3 * (GPLANE * 2);
#pragma unroll
        for (int kh = 0; kh < 2; kh++) {
            unsigned bh[4][2], bl[4][2];
#pragma unroll
            for (int ni = 0; ni < 4; ni++) {
                unsigned bo = boffs + (unsigned)((ni * 8 * SSTRIDE + kh * 16) * 2);
                ldsm2(bh[ni], bBh + bo);
                ldsm2(bl[ni], bBl + bo);
            }
#pragma unroll
            for (int mi = 0; mi < 4; mi++) {
                unsigned ah[4], al[4];
                unsigned ao = aoffs + (unsigned)((mi * 16 * SSTRIDE + kh * 16) * 2);
                ldsm4(ah, bAh + ao);
                ldsm4(al, bAl + ao);
#pragma unroll
                for (int ni = 0; ni < 4; ni++) {
                    mma16816(acc[mi][ni], ah, bh[ni]);
                    mma16816(acc[mi][ni], ah, bl[ni]);
                    mma16816(acc[mi][ni], al, bh[ni]);
                }
            }
        }
        __syncthreads();
        if (it + 2 < nkb) issue((it + 2) * 32, it & 1);
        else asm volatile("cp.async.commit_group;" ::: "memory");
    }

    int g = lane >> 2;
    int tig = lane & 3;

    if (EPI == 2 || EPI == 3) {
#pragma unroll
        for (int mi = 0; mi < 4; mi++)
#pragma unroll
            for (int ni = 0; ni < 4; ni++)
#pragma unroll
                for (int p = 0; p < 4; p++) acc[mi][ni][p] = siluf(acc[mi][ni][p]);
    }
    if (EPI == 2) {
#pragma unroll
        for (int mi = 0; mi < 4; mi++) {
            float s0 = 0.0f, s1 = 0.0f;
#pragma unroll
            for (int ni = 0; ni < 4; ni++) {
                s0 += acc[mi][ni][0] * acc[mi][ni][0] + acc[mi][ni][1] * acc[mi][ni][1];
                s1 += acc[mi][ni][2] * acc[mi][ni][2] + acc[mi][ni][3] * acc[mi][ni][3];
            }
            s0 += __shfl_xor_sync(0xffffffffu, s0, 1);
            s0 += __shfl_xor_sync(0xffffffffu, s0, 2);
            s1 += __shfl_xor_sync(0xffffffffu, s1, 1);
            s1 += __shfl_xor_sync(0xffffffffu, s1, 2);
            if (tig == 0) {
                red[wm * 64 + mi * 16 + g][wn] = s0;
                red[wm * 64 + mi * 16 + g + 8][wn] = s1;
            }
        }
        __syncthreads();
    }

#pragma unroll
    for (int mi = 0; mi < 4; mi++) {
        float sc0 = 1.0f, sc1 = 1.0f;
        if (EPI == 2) {
            int rl = wm * 64 + mi * 16 + g;
            float t0 = red[rl][0] + red[rl][1] + red[rl][2] + red[rl][3];
            float t1 = red[rl + 8][0] + red[rl + 8][1] + red[rl + 8][2] + red[rl + 8][3];
            sc0 = rsqrtf(t0 + 1e-6f);
            sc1 = rsqrtf(t1 + 1e-6f);
        }
#pragma unroll
        for (int ni = 0; ni < 4; ni++) {
            int row0 = bm + wm * 64 + mi * 16 + g;
            int col = bn + wn * 32 + ni * 8 + tig * 2;
            if (EPI == 1) {
                float s0 = siluf(acc[mi][ni][0]), s1 = siluf(acc[mi][ni][1]);
                float s2 = siluf(acc[mi][ni][2]), s3 = siluf(acc[mi][ni][3]);
                split_pair(s0, s1, &Chi[(size_t)row0 * N + col], &Clo[(size_t)row0 * N + col]);
                split_pair(s2, s3, &Chi[(size_t)(row0 + 8) * N + col], &Clo[(size_t)(row0 + 8) * N + col]);
            } else {
                float2 t0, t1;
                if (EPI == 4) {
                    float2 a0 = *(const float2*)&X1[(size_t)row0 * N + col];
                    float2 a1 = *(const float2*)&X1[(size_t)(row0 + 8) * N + col];
                    t0.x = a0.x + RES_SCALE * acc[mi][ni][0];
                    t0.y = a0.y + RES_SCALE * acc[mi][ni][1];
                    t1.x = a1.x + RES_SCALE * acc[mi][ni][2];
                    t1.y = a1.y + RES_SCALE * acc[mi][ni][3];
                } else if (EPI == 2) {
                    t0.x = acc[mi][ni][0] * sc0; t0.y = acc[mi][ni][1] * sc0;
                    t1.x = acc[mi][ni][2] * sc1; t1.y = acc[mi][ni][3] * sc1;
                } else {
                    t0.x = acc[mi][ni][0]; t0.y = acc[mi][ni][1];
                    t1.x = acc[mi][ni][2]; t1.y = acc[mi][ni][3];
                }
                *(float2*)&C[(size_t)row0 * N + col] = t0;
                *(float2*)&C[(size_t)(row0 + 8) * N + col] = t1;
            }
        }
    }
}

// ---------- fused weight split+transpose --------------------------------
__global__ void wsplit_all(const float* __restrict__ qw, const float* __restrict__ kw,
                           const float* __restrict__ vw, const float* __restrict__ gw,
                           const float* __restrict__ ow, const float* __restrict__ fcw,
                           const float* __restrict__ pw,
                           __nv_bfloat16* __restrict__ hi, __nv_bfloat16* __restrict__ lo) {
    int bid = blockIdx.x;
    const float* W;
    int K, N, t;
    size_t woff;
    if (bid < 5120) {
        int wsel = bid >> 10;
        t = bid & 1023; K = 1024; N = 1024;
        W = (wsel == 0) ? qw : (wsel == 1) ? kw : (wsel == 2) ? vw : (wsel == 3) ? gw : ow;
        woff = (size_t)wsel << 20;
    } else if (bid < 9216) {
        t = bid - 5120; K = 1024; N = 4096; W = fcw; woff = W_FCW;
    } else {
        t = bid - 9216; K = 4096; N = 1024; W = pw; woff = W_PW;
    }
    int ntiles = N >> 5;
    int nb = (t % ntiles) * 32, kb = (t / ntiles) * 32;
    __shared__ float tile[32][33];
    int tx = threadIdx.x & 31, ty = threadIdx.x >> 5;
#pragma unroll
    for (int i = 0; i < 32; i += 8)
        tile[ty + i][tx] = W[(size_t)(kb + ty + i) * N + nb + tx];
    __syncthreads();
#pragma unroll
    for (int i = 0; i < 32; i += 8) {
        float x = tile[tx][ty + i];
        size_t oidx = woff + (size_t)(nb + ty + i) * K + kb + tx;
        __nv_bfloat16 h = __float2bfloat16(x);
        hi[oidx] = h;
        lo[oidx] = __float2bfloat16(x - __bfloat162float(h));
    }
}

// -------------------- elementwise kernels --------------------------------
__global__ void rmsnorm_k(const float* __restrict__ x, const float* __restrict__ w,
                          float* __restrict__ out, __nv_bfloat16* __restrict__ ohi,
                          __nv_bfloat16* __restrict__ olo) {
    int row = blockIdx.x, tid = threadIdx.x;
    float4 v = ((const float4*)(x + (size_t)row * CD))[tid];
    float ss = v.x * v.x + v.y * v.y + v.z * v.z + v.w * v.w;
    __shared__ float red[8];
    int lane = tid & 31, warp = tid >> 5;
    ss = warpAllSum(ss);
    if (lane == 0) red[warp] = ss;
    __syncthreads();
    float tot = red[0] + red[1] + red[2] + red[3] + red[4] + red[5] + red[6] + red[7];
    float sc = rsqrtf(tot * (1.0f / CD) + 1e-6f);
    float4 wv = ((const float4*)w)[tid];
    float4 o;
    o.x = v.x * wv.x * sc; o.y = v.y * wv.y * sc;
    o.z = v.z * wv.z * sc; o.w = v.w * wv.w * sc;
    if (out) ((float4*)(out + (size_t)row * CD))[tid] = o;
    size_t e = (size_t)row * CD + tid * 4;
    split_pair(o.x, o.y, ohi + e, olo + e);
    split_pair(o.z, o.w, ohi + e + 2, olo + e + 2);
}

__global__ void resid_rms_k(const float* __restrict__ x, const float* __restrict__ a,
                            const float* __restrict__ w, float* __restrict__ x1,
                            __nv_bfloat16* __restrict__ h2h, __nv_bfloat16* __restrict__ h2l) {
    int row = blockIdx.x, tid = threadIdx.x;
    float4 xv = ((const float4*)(x + (size_t)row * CD))[tid];
    float4 av = ((const float4*)(a + (size_t)row * CD))[tid];
    float4 v;
    v.x = xv.x + RES_SCALE * av.x; v.y = xv.y + RES_SCALE * av.y;
    v.z = xv.z + RES_SCALE * av.z; v.w = xv.w + RES_SCALE * av.w;
    ((float4*)(x1 + (size_t)row * CD))[tid] = v;
    float ss = v.x * v.x + v.y * v.y + v.z * v.z + v.w * v.w;
    __shared__ float red[8];
    int lane = tid & 31, warp = tid >> 5;
    ss = warpAllSum(ss);
    if (lane == 0) red[warp] = ss;
    __syncthreads();
    float tot = red[0] + red[1] + red[2] + red[3] + red[4] + red[5] + red[6] + red[7];
    float sc = rsqrtf(tot * (1.0f / CD) + 1e-6f);
    float4 wv = ((const float4*)w)[tid];
    float4 o;
    o.x = v.x * wv.x * sc; o.y = v.y * wv.y * sc;
    o.z = v.z * wv.z * sc; o.w = v.w * wv.w * sc;
    size_t e = (size_t)row * CD + tid * 4;
    split_pair(o.x, o.y, h2h + e, h2l + e);
    split_pair(o.z, o.w, h2h + e + 2, h2l + e + 2);
}

__global__ void proj_bg_k(const float* __restrict__ h, const float* __restrict__ bw,
                          const float* __restrict__ aw, const float* __restrict__ A_log,
                          const float* __restrict__ dt_bias,
                          float* __restrict__ beta, float* __restrict__ eg) {
    int row = blockIdx.x, tid = threadIdx.x;
    float4 hv = ((const float4*)(h + (size_t)row * CD))[tid];
    float hx[4] = {hv.x, hv.y, hv.z, hv.w};
    float aB[8], aA[8];
#pragma unroll
    for (int j = 0; j < 8; j++) { aB[j] = 0.0f; aA[j] = 0.0f; }
#pragma unroll
    for (int i = 0; i < 4; i++) {
        int kk = tid * 4 + i;
        float xv = hx[i];
        float4 b0 = ((const float4*)(bw + (size_t)kk * CH))[0];
        float4 b1 = ((const float4*)(bw + (size_t)kk * CH))[1];
        float4 a0 = ((const float4*)(aw + (size_t)kk * CH))[0];
        float4 a1 = ((const float4*)(aw + (size_t)kk * CH))[1];
        aB[0] = fmaf(xv, b0.x, aB[0]); aB[1] = fmaf(xv, b0.y, aB[1]);
        aB[2] = fmaf(xv, b0.z, aB[2]); aB[3] = fmaf(xv, b0.w, aB[3]);
        aB[4] = fmaf(xv, b1.x, aB[4]); aB[5] = fmaf(xv, b1.y, aB[5]);
        aB[6] = fmaf(xv, b1.z, aB[6]); aB[7] = fmaf(xv, b1.w, aB[7]);
        aA[0] = fmaf(xv, a0.x, aA[0]); aA[1] = fmaf(xv, a0.y, aA[1]);
        aA[2] = fmaf(xv, a0.z, aA[2]); aA[3] = fmaf(xv, a0.w, aA[3]);
        aA[4] = fmaf(xv, a1.x, aA[4]); aA[5] = fmaf(xv, a1.y, aA[5]);
        aA[6] = fmaf(xv, a1.z, aA[6]); aA[7] = fmaf(xv, a1.w, aA[7]);
    }
#pragma unroll
    for (int j = 0; j < 8; j++) { aB[j] = warpAllSum(aB[j]); aA[j] = warpAllSum(aA[j]); }
    __shared__ float red[8][16];
    int lane = tid & 31, warp = tid >> 5;
    if (lane == 0) {
#pragma unroll
        for (int j = 0; j < 8; j++) { red[warp][j] = aB[j]; red[warp][j + 8] = aA[j]; }
    }
    __syncthreads();
    if (tid < 16) {
        float s = 0.0f;
#pragma unroll
        for (int w = 0; w < 8; w++) s += red[w][tid];
        if (tid < 8) {
            beta[(size_t)row * CH + tid] = 1.0f / (1.0f + expf(-s));
        } else {
            int j = tid - 8;
            float z = s + dt_bias[j];
            float sp = (z > 20.0f) ? z : log1pf(expf(z));
            float gg = -expf(A_log[j]) * sp;
            eg[(size_t)row * CH + j] = expf(gg);
        }
    }
}

__global__ void onorm_gate_k(const float* __restrict__ o, const float* __restrict__ gate,
                             const float* __restrict__ onw,
                             __nv_bfloat16* __restrict__ oh, __nv_bfloat16* __restrict__ ol) {
    int row = blockIdx.x;
    int lane = threadIdx.x & 31, warp = threadIdx.x >> 5;
    size_t base4 = (size_t)row * (CD / 4) + warp * (CHD / 4) + lane;
    float4 ov = ((const float4*)o)[base4];
    float ss = warpAllSum(ov.x * ov.x + ov.y * ov.y + ov.z * ov.z + ov.w * ov.w);
    float sc = rsqrtf(ss * (1.0f / CHD) + 1e-6f);
    float4 gv = ((const float4*)gate)[base4];
    gv.x = siluf(gv.x); gv.y = siluf(gv.y); gv.z = siluf(gv.z); gv.w = siluf(gv.w);
    float4 wv = ((const float4*)onw)[lane];
    float4 r;
    r.x = ov.x * sc * wv.x * gv.x;
    r.y = ov.y * sc * wv.y * gv.y;
    r.z = ov.z * sc * wv.z * gv.z;
    r.w = ov.w * sc * wv.w * gv.w;
    size_t e = base4 * 4;
    split_pair(r.x, r.y, oh + e, ol + e);
    split_pair(r.z, r.w, oh + e + 2, ol + e + 2);
}

// --------- pairwise dots: for each token pair (2i,2i+1) per (b,h) ----------
// dots = {k1.k2, q1.k1, q2.k1, q2.k2}
__global__ __launch_bounds__(256) void scan_dots(
    const float* __restrict__ q, const float* __restrict__ k,
    float* __restrict__ dots) {
    int wgid = blockIdx.x * 8 + (threadIdx.x >> 5);   // 0..32767
    int lane = threadIdx.x & 31;
    int bh = wgid >> 10, i = wgid & 1023;
    int b = bh >> 3, h = bh & 7;
    size_t idx0 = ((size_t)b * CT + 2 * i) * CH + h;
    size_t idx1 = idx0 + CH;
    float4 k1 = ((const float4*)(k + idx0 * CHD))[lane];
    float4 k2 = ((const float4*)(k + idx1 * CHD))[lane];
    float4 q1 = ((const float4*)(q + idx0 * CHD))[lane];
    float4 q2 = ((const float4*)(q + idx1 * CHD))[lane];
    float dk12 = k1.x * k2.x + k1.y * k2.y + k1.z * k2.z + k1.w * k2.w;
    float dq1k1 = q1.x * k1.x + q1.y * k1.y + q1.z * k1.z + q1.w * k1.w;
    float dq2k1 = q2.x * k1.x + q2.y * k1.y + q2.z * k1.z + q2.w * k1.w;
    float dq2k2 = q2.x * k2.x + q2.y * k2.y + q2.z * k2.z + q2.w * k2.w;
    dk12 = warpAllSum(dk12);
    dq1k1 = warpAllSum(dq1k1);
    dq2k1 = warpAllSum(dq2k1);
    dq2k2 = warpAllSum(dq2k2);
    if (lane == 0) {
        float4 o; o.x = dk12; o.y = dq1k1; o.z = dq2k1; o.w = dq2k2;
        ((float4*)dots)[((size_t)b * NPAIR + i) * CH + h] = o;
    }
}

// -------------------- gated delta-rule scan: 2 tokens / iteration ---------
// 512 CTAs x 1 warp: (b,h) x 16 col-groups of 8. lane = colL(8) x seg(4).
// Per pair: one S read-pass (4 GEMVs), one shfl round, scalars with
// precomputed dots, one fused S update, 2 o-writes. 1024 iterations.
#define SC_ST 4
__global__ __launch_bounds__(32) void scan_k(
    const float* __restrict__ q, const float* __restrict__ k,
    const float* __restrict__ v, const float* __restrict__ beta,
    const float* __restrict__ eg, const float* __restrict__ dots,
    float* __restrict__ o, float* __restrict__ sf) {
    __shared__ float sk1[SC_ST][128];
    __shared__ float sq1[SC_ST][128];
    __shared__ float sk2[SC_ST][128];
    __shared__ float sq2[SC_ST][128];
    __shared__ float sv[SC_ST][32];  // v1[0..7] v2[8..15] eg1 eg2 b1 b2 @16..19, dots @20..23

    int wg = blockIdx.x;
    int bh = wg >> 4, cg = wg & 15;
    int b = bh >> 3, hh = bh & 7;
    int lane = threadIdx.x;
    int colL = lane >> 2;
    int col = cg * 8 + colL;
    int seg = lane & 3;

    unsigned sk1b = (unsigned)__cvta_generic_to_shared(sk1);
    unsigned sq1b = (unsigned)__cvta_generic_to_shared(sq1);
    unsigned sk2b = (unsigned)__cvta_generic_to_shared(sk2);
    unsigned sq2b = (unsigned)__cvta_generic_to_shared(sq2);
    unsigned svb = (unsigned)__cvta_generic_to_shared(sv);

    int rowbase = b * CT * CH + hh;
    const float* dbase = dots + ((size_t)b * NPAIR * CH + hh) * 4;

    auto issue = [&](int i) {
        if (i < NPAIR) {
            int idx0 = rowbase + 2 * i * CH;
            int idx1 = idx0 + CH;
            int st = i & (SC_ST - 1);
            unsigned lo4 = (unsigned)((st * 128 + lane * 4) * 4);
            cpa16(sk1b + lo4, k + (size_t)idx0 * CHD + lane * 4);
            cpa16(sq1b + lo4, q + (size_t)idx0 * CHD + lane * 4);
            cpa16(sk2b + lo4, k + (size_t)idx1 * CHD + lane * 4);
            cpa16(sq2b + lo4, q + (size_t)idx1 * CHD + lane * 4);
            if (lane < 8)
                cpa4(svb + (unsigned)((st * 32 + lane) * 4), v + (size_t)idx0 * CHD + cg * 8 + lane);
            else if (lane < 16)
                cpa4(svb + (unsigned)((st * 32 + lane) * 4), v + (size_t)idx1 * CHD + cg * 8 + (lane - 8));
            else if (lane == 16)
                cpa4(svb + (unsigned)((st * 32 + 16) * 4), eg + idx0);
            else if (lane == 17)
                cpa4(svb + (unsigned)((st * 32 + 17) * 4), eg + idx1);
            else if (lane == 18)
                cpa4(svb + (unsigned)((st * 32 + 18) * 4), beta + idx0);
            else if (lane == 19)
                cpa4(svb + (unsigned)((st * 32 + 19) * 4), beta + idx1);
            else if (lane == 20)
                cpa16(svb + (unsigned)((st * 32 + 20) * 4), dbase + (size_t)i * CH * 4);
        }
        asm volatile("cp.async.commit_group;" ::: "memory");
    };

    issue(0); issue(1); issue(2);

    float S[32];
#pragma unroll
    for (int j = 0; j < 32; j++) S[j] = 0.0f;

    for (int i = 0; i < NPAIR; i++) {
        int st = i & (SC_ST - 1);
        asm volatile("cp.async.wait_group 2;" ::: "memory");
        __syncwarp();
        const float* kp1 = &sk1[st][seg * 32];
        const float* qp1 = &sq1[st][seg * 32];
        const float* kp2 = &sk2[st][seg * 32];
        const float* qp2 = &sq2[st][seg * 32];
        float v1 = sv[st][colL], v2 = sv[st][8 + colL];
        float eg1 = sv[st][16], eg2 = sv[st][17];
        float b1 = sv[st][18], b2 = sv[st][19];
        float dk12 = sv[st][20], dq1k1 = sv[st][21];
        float dq2k1 = sv[st][22], dq2k2 = sv[st][23];

        float kr1[32], kr2[32];
        float ak1a = 0.0f, ak1b = 0.0f, ak2a = 0.0f, ak2b = 0.0f;
        float aq1a = 0.0f, aq1b = 0.0f, aq2a = 0.0f, aq2b = 0.0f;
#pragma unroll
        for (int j = 0; j < 32; j += 2) {
            float s0 = S[j], s1 = S[j + 1];
            float k1a = kp1[j], k1b = kp1[j + 1];
            float k2a = kp2[j], k2b = kp2[j + 1];
            kr1[j] = k1a; kr1[j + 1] = k1b;
            kr2[j] = k2a; kr2[j + 1] = k2b;
            ak1a = fmaf(k1a, s0, ak1a); ak1b = fmaf(k1b, s1, ak1b);
            ak2a = fmaf(k2a, s0, ak2a); ak2b = fmaf(k2b, s1, ak2b);
            aq1a = fmaf(qp1[j], s0, aq1a); aq1b = fmaf(qp1[j + 1], s1, aq1b);
            aq2a = fmaf(qp2[j], s0, aq2a); aq2b = fmaf(qp2[j + 1], s1, aq2b);
        }
        float ak1 = ak1a + ak1b, ak2 = ak2a + ak2b;
        float aq1 = aq1a + aq1b, aq2 = aq2a + aq2b;
        ak1 += __shfl_xor_sync(0xffffffffu, ak1, 1);
        ak1 += __shfl_xor_sync(0xffffffffu, ak1, 2);
        ak2 += __shfl_xor_sync(0xffffffffu, ak2, 1);
        ak2 += __shfl_xor_sync(0xffffffffu, ak2, 2);
        aq1 += __shfl_xor_sync(0xffffffffu, aq1, 1);
        aq1 += __shfl_xor_sync(0xffffffffu, aq1, 2);
        aq2 += __shfl_xor_sync(0xffffffffu, aq2, 1);
        aq2 += __shfl_xor_sync(0xffffffffu, aq2, 2);

        float e12 = eg1 * eg2;
        float bd1 = b1 * (v1 - eg1 * ak1);
        float o1 = fmaf(dq1k1, bd1, eg1 * aq1);
        float bd2 = b2 * (v2 - e12 * ak2 - eg2 * dk12 * bd1);
        float o2 = fmaf(dq2k2, bd2, fmaf(eg2 * dq2k1, bd1, e12 * aq2));
        float c1 = eg2 * bd1, c2 = bd2;

#pragma unroll
        for (int j = 0; j < 32; j++)
            S[j] = fmaf(kr2[j], c2, fmaf(kr1[j], c1, e12 * S[j]));

        if (seg == 0) {
            int idx0 = rowbase + 2 * i * CH;
            o[(size_t)idx0 * CHD + col] = o1;
            o[(size_t)(idx0 + CH) * CHD + col] = o2;
        }
        issue(i + 3);
    }

    float* sfp = sf + ((size_t)bh * CHD + seg * 32) * CHD + col;
#pragma unroll
    for (int j = 0; j < 32; j++) sfp[(size_t)j * CHD] = S[j];
}

// -------------------- launcher --------------------------------------------
static float* symaddrf(const void* sym) {
    void* p = nullptr;
    cudaGetSymbolAddress(&p, sym);
    return (float*)p;
}
static __nv_bfloat16* symaddrb(const void* sym) {
    void* p = nullptr;
    cudaGetSymbolAddress(&p, sym);
    return (__nv_bfloat16*)p;
}

extern "C" void kernel_launch(void* const* d_in, const int* in_sizes, int n_in,
                              void* d_out, int out_size) {
    const float* x       = (const float*)d_in[0];
    const float* ln1_w   = (const float*)d_in[1];
    const float* qw      = (const float*)d_in[2];
    const float* kw      = (const float*)d_in[3];
    const float* vw      = (const float*)d_in[4];
    const float* bw      = (const float*)d_in[5];
    const float* aw      = (const float*)d_in[6];
    const float* A_log   = (const float*)d_in[7];
    const float* dt_bias = (const float*)d_in[8];
    const float* gw      = (const float*)d_in[9];
    const float* onorm_w = (const float*)d_in[10];
    const float* ow      = (const float*)d_in[11];
    const float* ln2_w   = (const float*)d_in[12];
    const float* fcw     = (const float*)d_in[13];
    const float* pw      = (const float*)d_in[14];
    float* y = (float*)d_out;

    float* h_    = symaddrf(g_h);
    float* q_    = symaddrf(g_q);
    float* k_    = symaddrf(g_k);
    float* v_    = symaddrf(g_v);
    float* gate_ = symaddrf(g_gate);
    float* o_    = symaddrf(g_o);
    float* attn_ = symaddrf(g_attn);
    float* x1_   = symaddrf(g_x1);
    float* beta_ = symaddrf(g_beta);
    float* eg_   = symaddrf(g_eg);
    float* dots_ = symaddrf(g_dots);
    float* sfd_  = symaddrf(g_sfdummy);

    __nv_bfloat16* hh_   = symaddrb(g_hh);
    __nv_bfloat16* hl_   = symaddrb(g_hl);
    __nv_bfloat16* h2h_  = symaddrb(g_h2h);
    __nv_bfloat16* h2l_  = symaddrb(g_h2l);
    __nv_bfloat16* oh_   = symaddrb(g_oh);
    __nv_bfloat16* ol_   = symaddrb(g_ol);
    __nv_bfloat16* mlph_ = symaddrb(g_mlph);
    __nv_bfloat16* mlpl_ = symaddrb(g_mlpl);
    __nv_bfloat16* wth_  = symaddrb(g_wth);
    __nv_bfloat16* wtl_  = symaddrb(g_wtl);

    float* sfdst = (out_size >= YTOT + STOT) ? (y + YTOT) : sfd_;

    static int smem_set = 0;
    if (!smem_set) {
        cudaFuncSetAttribute(gemm_tc<0>, cudaFuncAttributeMaxDynamicSharedMemorySize, GSMEM);
        cudaFuncSetAttribute(gemm_tc<1>, cudaFuncAttributeMaxDynamicSharedMemorySize, GSMEM);
        cudaFuncSetAttribute(gemm_tc<2>, cudaFuncAttributeMaxDynamicSharedMemorySize, GSMEM);
        cudaFuncSetAttribute(gemm_tc<3>, cudaFuncAttributeMaxDynamicSharedMemorySize, GSMEM);
        cudaFuncSetAttribute(gemm_tc<4>, cudaFuncAttributeMaxDynamicSharedMemorySize, GSMEM);
        smem_set = 1;
    }

    dim3 blk(256);
    dim3 g1024(1024 / 128, CM / 128);
    dim3 g4096(4096 / 128, CM / 128);

    rmsnorm_k<<<CM, blk>>>(x, ln1_w, h_, hh_, hl_);
    wsplit_all<<<13312, blk>>>(qw, kw, vw, gw, ow, fcw, pw, wth_, wtl_);
    gemm_tc<2><<<g1024, blk, GSMEM>>>(hh_, hl_, wth_ + W_QW, wtl_ + W_QW, q_, nullptr, nullptr, nullptr, CM, CD, CD);
    gemm_tc<2><<<g1024, blk, GSMEM>>>(hh_, hl_, wth_ + W_KW, wtl_ + W_KW, k_, nullptr, nullptr, nullptr, CM, CD, CD);
    gemm_tc<3><<<g1024, blk, GSMEM>>>(hh_, hl_, wth_ + W_VW, wtl_ + W_VW, v_, nullptr, nullptr, nullptr, CM, CD, CD);
    gemm_tc<0><<<g1024, blk, GSMEM>>>(hh_, hl_, wth_ + W_GW, wtl_ + W_GW, gate_, nullptr, nullptr, nullptr, CM, CD, CD);

    proj_bg_k<<<CM, blk>>>(h_, bw, aw, A_log, dt_bias, beta_, eg_);
    scan_dots<<<4096, blk>>>(q_, k_, dots_);
    scan_k<<<512, 32>>>(q_, k_, v_, beta_, eg_, dots_, o_, sfdst);
    onorm_gate_k<<<CM, blk>>>(o_, gate_, onorm_w, oh_, ol_);

    gemm_tc<0><<<g1024, blk, GSMEM>>>(oh_, ol_, wth_ + W_OW, wtl_ + W_OW, attn_, nullptr, nullptr, nullptr, CM, CD, CD);
    resid_rms_k<<<CM, blk>>>(x, attn_, ln2_w, x1_, h2h_, h2l_);

    gemm_tc<1><<<g4096, blk, GSMEM>>>(h2h_, h2l_, wth_ + W_FCW, wtl_ + W_FCW, nullptr, mlph_, mlpl_, nullptr, CM, 4 * CD, CD);
    gemm_tc<4><<<g1024, blk, GSMEM>>>(mlph_, mlpl_, wth_ + W_PW, wtl_ + W_PW, y, nullptr, nullptr, x1_, CM, CD, 4 * CD);
}